// round 9
// baseline (speedup 1.0000x reference)
#include <cuda_runtime.h>
#include <math.h>

#define T 8192
#define D 4096
#define E 8
#define KSEL 2
#define SLOTS (T * KSEL)
#define NHB 64             // hist blocks
#define SPB (SLOTS / NHB)  // 256 slots per hist block
#define RSU 1024           // ulonglong2 (16B) per D-row
#define NG2 (T / 2)        // 4096 warp-tasks (2 tokens each)
#define SGRID 148

// Output layout (float32, concatenated in reference-return order)
#define OFF_XG  0
#define OFF_CNT 67108864ll   // 16384*4096
#define OFF_IDX 67108872ll
#define OFF_SC  67125256ll

// Scratch (no allocations allowed -> __device__ globals)
__device__ int   g_exp[SLOTS];
__device__ float g_prob[SLOTS];
__device__ int   g_pos[SLOTS];
__device__ int   g_bhist[NHB * E];
__device__ volatile int g_sync;  // rank kernel global barrier (self-resetting)
__device__ int   g_done;

// packed f32x2 fma: d = a*b + d
__device__ __forceinline__ void fma2(unsigned long long& d,
                                     unsigned long long a,
                                     unsigned long long b) {
    asm("fma.rn.f32x2 %0, %1, %2, %0;" : "+l"(d) : "l"(a), "l"(b));
}
__device__ __forceinline__ float unpack_add(unsigned long long v) {
    float lo, hi;
    asm("mov.b64 {%0, %1}, %2;" : "=f"(lo), "=f"(hi) : "l"(v));
    return lo + hi;
}

// ---------------------------------------------------------------------------
// Kernel A: router scores + top-2 + softmax.
// FULL W (128KB) staged once in dynamic SMEM -> barrier-free mainloop.
// grid=148, 1024 threads = 32 warps/SM (2x R8 occupancy). 2 tokens/warp,
// task g = w*148 + blk over 4096 tasks (~27.7 active warps per SM).
// acc = 32 regs -> fits 64-reg cap with batched x loads.
// ---------------------------------------------------------------------------
extern __shared__ ulonglong2 Ws[];   // [e * 1024 + i], 128KB

__global__ void __launch_bounds__(1024, 1) router_scores_kernel(
    const float* __restrict__ x, const float* __restrict__ W)
{
    const int tid  = threadIdx.x;
    const int w    = tid >> 5;
    const int lane = tid & 31;

    const ulonglong2* __restrict__ x2 = (const ulonglong2*)x;
    const ulonglong2* __restrict__ w2 = (const ulonglong2*)W;

    // stage full W: 8192 ulonglong2, 8 per thread, coalesced
#pragma unroll
    for (int k = 0; k < 8; k++) {
        const int idx = tid + k * 1024;
        Ws[idx] = w2[idx];
    }
    __syncthreads();

    const int g = w * SGRID + blockIdx.x;
    if (g >= NG2) return;
    const int t0 = g * 2;

    const size_t xb = (size_t)t0 * RSU;
    unsigned long long acc[2][E];
#pragma unroll
    for (int j = 0; j < 2; j++)
#pragma unroll
        for (int e = 0; e < E; e++) acc[j][e] = 0ull;

#pragma unroll 2
    for (int it = 0; it < 32; it++) {
        const int i = it * 32 + lane;
        ulonglong2 xv0 = x2[xb + i];
        ulonglong2 xv1 = x2[xb + RSU + i];
#pragma unroll
        for (int e = 0; e < E; e++) {
            ulonglong2 wv = Ws[e * RSU + i];
            fma2(acc[0][e], xv0.x, wv.x); fma2(acc[0][e], xv0.y, wv.y);
            fma2(acc[1][e], xv1.x, wv.x); fma2(acc[1][e], xv1.y, wv.y);
        }
    }

    // collapse packed halves, then warp tree-reduce 16 scalars
    float s[2][E];
#pragma unroll
    for (int j = 0; j < 2; j++)
#pragma unroll
        for (int e = 0; e < E; e++) s[j][e] = unpack_add(acc[j][e]);

#pragma unroll
    for (int off = 16; off > 0; off >>= 1) {
#pragma unroll
        for (int j = 0; j < 2; j++)
#pragma unroll
            for (int e = 0; e < E; e++)
                s[j][e] += __shfl_xor_sync(0xffffffffu, s[j][e], off);
    }

    // lanes 0..1 finalize token t0+lane
#pragma unroll
    for (int j = 0; j < 2; j++) {
        if (lane == j) {
            const int t = t0 + j;
            // stable top-2 (first occurrence wins ties, matching jax.lax.top_k)
            float b0 = -3.4e38f, b1 = -3.4e38f;
            int i0 = 0, i1 = 0;
#pragma unroll
            for (int e = 0; e < E; e++) {
                float v = s[j][e];
                if (v > b0) { b1 = b0; i1 = i0; b0 = v; i0 = e; }
                else if (v > b1) { b1 = v; i1 = e; }
            }
            float ex = expf(b1 - b0);
            float inv = 1.f / (1.f + ex);
            ((int2*)g_exp)[t]    = make_int2(i0, i1);
            ((float2*)g_prob)[t] = make_float2(inv, ex * inv);
        }
    }
}

// ---------------------------------------------------------------------------
// Packed per-expert counters: 8 experts x 8-bit fields across two uints.
// ---------------------------------------------------------------------------
__device__ __forceinline__ void packAdd(int e, unsigned& lo, unsigned& hi) {
    if (e < 4) lo += 1u << (8 * e);
    else       hi += 1u << (8 * (e - 4));
}
__device__ __forceinline__ int fieldOf(unsigned lo, unsigned hi, int e) {
    unsigned v = (e < 4) ? lo : hi;
    return (int)((v >> (8 * (e & 3))) & 0xffu);
}

// ---------------------------------------------------------------------------
// Kernel B: fused rank (hist + global barrier + finalize), 64 blocks x 256.
// All 64 blocks co-resident (64 < 148 SMs) -> spin barrier safe.
// Counters self-reset for graph replay determinism.
// ---------------------------------------------------------------------------
__global__ void __launch_bounds__(SPB) rank_kernel(float* __restrict__ out)
{
    __shared__ unsigned wlo[8], whi[8];
    __shared__ int offE[E], totE[E], baseE[E];

    const int b    = blockIdx.x;
    const int tid  = threadIdx.x;
    const int wid  = tid >> 5;
    const int lane = tid & 31;
    const int slot = b * SPB + tid;

    // ---- phase 1: local stable rank + per-block histogram ----
    const int e = g_exp[slot];
    unsigned lo = 0, hi = 0;
    packAdd(e, lo, hi);
    const unsigned mlo = lo, mhi = hi;

#pragma unroll
    for (int off = 1; off < 32; off <<= 1) {
        unsigned vlo = __shfl_up_sync(0xffffffffu, lo, off);
        unsigned vhi = __shfl_up_sync(0xffffffffu, hi, off);
        if (lane >= off) { lo += vlo; hi += vhi; }
    }
    if (lane == 31) { wlo[wid] = lo; whi[wid] = hi; }
    __syncthreads();

    unsigned plo = 0, phi = 0;
#pragma unroll
    for (int w2 = 0; w2 < 8; w2++)
        if (w2 < wid) { plo += wlo[w2]; phi += whi[w2]; }

    const int lrank = fieldOf(plo + lo - mlo, phi + hi - mhi, e);

    if (tid < E) {
        unsigned tlo = 0, thi = 0;
#pragma unroll
        for (int w2 = 0; w2 < 8; w2++) { tlo += wlo[w2]; thi += whi[w2]; }
        g_bhist[b * E + tid] = fieldOf(tlo, thi, tid);
    }

    // ---- global barrier across the 64 blocks ----
    __threadfence();
    __syncthreads();
    if (tid == 0) atomicAdd((int*)&g_sync, 1);
    if (tid == 0) while (g_sync < NHB) { }
    __syncthreads();
    __threadfence();

    // ---- phase 2: finalize ----
    if (tid < E) {
        int off = 0, tot = 0;
#pragma unroll
        for (int bb = 0; bb < NHB; bb++) {
            int h = g_bhist[bb * E + tid];
            if (bb < b) off += h;
            tot += h;
        }
        offE[tid] = off; totE[tid] = tot;
    }
    __syncthreads();
    if (tid == 0) {
        int s = 0;
#pragma unroll
        for (int ee = 0; ee < E; ee++) { baseE[ee] = s; s += totE[ee]; }
    }
    __syncthreads();

    const int pos = baseE[e] + offE[e] + lrank;
    g_pos[slot] = pos;
    out[OFF_IDX + pos] = (float)(slot >> 1);   // scatter_indices
    out[OFF_SC  + pos] = g_prob[slot];         // scores_sorted

    if (b == 0 && tid < E) out[OFF_CNT + tid] = (float)totE[tid];

    // ---- self-reset for next graph replay ----
    __syncthreads();
    if (tid == 0) {
        int d = atomicAdd(&g_done, 1);
        if (d == NHB - 1) { g_sync = 0; g_done = 0; }
    }
}

// ---------------------------------------------------------------------------
// Kernel C: scatter copy — read each token row once, write 2 destination rows.
// ---------------------------------------------------------------------------
__global__ void __launch_bounds__(256) scatter_kernel(
    const float* __restrict__ x, float* __restrict__ out)
{
    const int t = blockIdx.x;
    const int p0 = g_pos[2 * t];
    const int p1 = g_pos[2 * t + 1];
    const float4* __restrict__ src = (const float4*)x + (size_t)t * 1024;
    float4* __restrict__ d0 = (float4*)(out + OFF_XG) + (size_t)p0 * 1024;
    float4* __restrict__ d1 = (float4*)(out + OFF_XG) + (size_t)p1 * 1024;

    const int i = threadIdx.x;
    float4 v0 = src[i];
    float4 v1 = src[i + 256];
    float4 v2 = src[i + 512];
    float4 v3 = src[i + 768];
    __stcs(d0 + i,       v0);
    __stcs(d0 + i + 256, v1);
    __stcs(d0 + i + 512, v2);
    __stcs(d0 + i + 768, v3);
    __stcs(d1 + i,       v0);
    __stcs(d1 + i + 256, v1);
    __stcs(d1 + i + 512, v2);
    __stcs(d1 + i + 768, v3);
}

extern "C" void kernel_launch(void* const* d_in, const int* in_sizes, int n_in,
                              void* d_out, int out_size)
{
    const float* x = (const float*)d_in[0];
    const float* W = (const float*)d_in[1];
    if (n_in >= 2 && in_sizes[0] == E * D && in_sizes[1] == (int)((size_t)T * D)) {
        const float* tmp = x; x = W; W = tmp;
    }
    float* out = (float*)d_out;

    static int smem_set = 0;
    if (!smem_set) {
        cudaFuncSetAttribute(router_scores_kernel,
                             cudaFuncAttributeMaxDynamicSharedMemorySize,
                             E * D * (int)sizeof(float));
        smem_set = 1;
    }

    router_scores_kernel<<<SGRID, 1024, E * D * sizeof(float)>>>(x, W);
    rank_kernel<<<NHB, SPB>>>(out);
    scatter_kernel<<<T, 256>>>(x, out);
}

// round 10
// speedup vs baseline: 1.0800x; 1.0800x over previous
#include <cuda_runtime.h>
#include <math.h>

#define T 8192
#define D 4096
#define E 8
#define KSEL 2
#define SLOTS (T * KSEL)
#define NHB 64             // hist blocks
#define SPB (SLOTS / NHB)  // 256 slots per hist block
#define RSF 1024           // float4 per D-row
#define NG4 (T / 4)        // 2048 warp-tasks (4 tokens each)
#define SGRID 148

// Output layout (float32, concatenated in reference-return order)
#define OFF_XG  0
#define OFF_CNT 67108864ll   // 16384*4096
#define OFF_IDX 67108872ll
#define OFF_SC  67125256ll

// Scratch (no allocations allowed -> __device__ globals)
__device__ int   g_exp[SLOTS];
__device__ float g_prob[SLOTS];
__device__ int   g_pos[SLOTS];
__device__ int   g_bhist[NHB * E];
__device__ volatile int g_sync;  // rank kernel global barrier (self-resetting)
__device__ int   g_done;

// ---------------------------------------------------------------------------
// Kernel A: router scores + top-2 + softmax.
// FULL W (128KB) staged once in dynamic SMEM -> barrier-free mainloop.
// grid=148, 512 threads = 16 warps. 4 tokens/warp (2:1 LDS:x wavefronts),
// task g = w*148 + blk over 2048 tasks (13-14 active warps/SM).
// SCALAR fp32 acc (32 regs) frees registers for a 2-deep x prefetch
// (two rolling 4x float4 buffers -> 4KB in flight per warp).
// ---------------------------------------------------------------------------
extern __shared__ float4 Ws[];   // [e * 1024 + i], 128KB

__global__ void __launch_bounds__(512, 1) router_scores_kernel(
    const float* __restrict__ x, const float* __restrict__ W)
{
    const int tid  = threadIdx.x;
    const int w    = tid >> 5;
    const int lane = tid & 31;

    const float4* __restrict__ x4 = (const float4*)x;
    const float4* __restrict__ w4 = (const float4*)W;

    // stage full W: 8192 float4, 16 per thread, coalesced
#pragma unroll
    for (int k = 0; k < 16; k++) {
        const int idx = tid + k * 512;
        Ws[idx] = w4[idx];
    }
    __syncthreads();

    const int g = w * SGRID + blockIdx.x;
    if (g >= NG4) return;
    const int t0 = g * 4;

    const float4* __restrict__ xr0 = x4 + (size_t)t0 * RSF;
    const float4* __restrict__ xr1 = xr0 + RSF;
    const float4* __restrict__ xr2 = xr0 + 2 * RSF;
    const float4* __restrict__ xr3 = xr0 + 3 * RSF;

    float acc[4][E];
#pragma unroll
    for (int j = 0; j < 4; j++)
#pragma unroll
        for (int e = 0; e < E; e++) acc[j][e] = 0.f;

    // rolling buffers: A holds even iterations, B odd; prefetch depth 2
    float4 A0 = xr0[lane],      A1 = xr1[lane],
           A2 = xr2[lane],      A3 = xr3[lane];
    float4 B0 = xr0[32 + lane], B1 = xr1[32 + lane],
           B2 = xr2[32 + lane], B3 = xr3[32 + lane];

#pragma unroll 2
    for (int k = 0; k < 16; k++) {
        // ---- even iteration 2k (buffer A) ----
        {
            const int i = 2 * k * 32 + lane;
            float4 xa0 = A0, xa1 = A1, xa2 = A2, xa3 = A3;
            if (2 * k + 2 < 32) {
                const int ni = (2 * k + 2) * 32 + lane;
                A0 = xr0[ni]; A1 = xr1[ni]; A2 = xr2[ni]; A3 = xr3[ni];
            }
#pragma unroll
            for (int e = 0; e < E; e++) {
                float4 wv = Ws[e * RSF + i];
                acc[0][e] += xa0.x * wv.x + xa0.y * wv.y + xa0.z * wv.z + xa0.w * wv.w;
                acc[1][e] += xa1.x * wv.x + xa1.y * wv.y + xa1.z * wv.z + xa1.w * wv.w;
                acc[2][e] += xa2.x * wv.x + xa2.y * wv.y + xa2.z * wv.z + xa2.w * wv.w;
                acc[3][e] += xa3.x * wv.x + xa3.y * wv.y + xa3.z * wv.z + xa3.w * wv.w;
            }
        }
        // ---- odd iteration 2k+1 (buffer B) ----
        {
            const int i = (2 * k + 1) * 32 + lane;
            float4 xb0 = B0, xb1 = B1, xb2 = B2, xb3 = B3;
            if (2 * k + 3 < 32) {
                const int ni = (2 * k + 3) * 32 + lane;
                B0 = xr0[ni]; B1 = xr1[ni]; B2 = xr2[ni]; B3 = xr3[ni];
            }
#pragma unroll
            for (int e = 0; e < E; e++) {
                float4 wv = Ws[e * RSF + i];
                acc[0][e] += xb0.x * wv.x + xb0.y * wv.y + xb0.z * wv.z + xb0.w * wv.w;
                acc[1][e] += xb1.x * wv.x + xb1.y * wv.y + xb1.z * wv.z + xb1.w * wv.w;
                acc[2][e] += xb2.x * wv.x + xb2.y * wv.y + xb2.z * wv.z + xb2.w * wv.w;
                acc[3][e] += xb3.x * wv.x + xb3.y * wv.y + xb3.z * wv.z + xb3.w * wv.w;
            }
        }
    }

    // warp tree-reduce 32 scalars
#pragma unroll
    for (int off = 16; off > 0; off >>= 1) {
#pragma unroll
        for (int j = 0; j < 4; j++)
#pragma unroll
            for (int e = 0; e < E; e++)
                acc[j][e] += __shfl_xor_sync(0xffffffffu, acc[j][e], off);
    }

    // lanes 0..3 finalize token t0+lane
#pragma unroll
    for (int j = 0; j < 4; j++) {
        if (lane == j) {
            const int t = t0 + j;
            // stable top-2 (first occurrence wins ties, matching jax.lax.top_k)
            float b0 = -3.4e38f, b1 = -3.4e38f;
            int i0 = 0, i1 = 0;
#pragma unroll
            for (int e = 0; e < E; e++) {
                float v = acc[j][e];
                if (v > b0) { b1 = b0; i1 = i0; b0 = v; i0 = e; }
                else if (v > b1) { b1 = v; i1 = e; }
            }
            float ex = expf(b1 - b0);
            float inv = 1.f / (1.f + ex);
            ((int2*)g_exp)[t]    = make_int2(i0, i1);
            ((float2*)g_prob)[t] = make_float2(inv, ex * inv);
        }
    }
}

// ---------------------------------------------------------------------------
// Packed per-expert counters: 8 experts x 8-bit fields across two uints.
// ---------------------------------------------------------------------------
__device__ __forceinline__ void packAdd(int e, unsigned& lo, unsigned& hi) {
    if (e < 4) lo += 1u << (8 * e);
    else       hi += 1u << (8 * (e - 4));
}
__device__ __forceinline__ int fieldOf(unsigned lo, unsigned hi, int e) {
    unsigned v = (e < 4) ? lo : hi;
    return (int)((v >> (8 * (e & 3))) & 0xffu);
}

// ---------------------------------------------------------------------------
// Kernel B: fused rank (hist + global barrier + finalize), 64 blocks x 256.
// All 64 blocks co-resident (64 < 148 SMs) -> spin barrier safe.
// Counters self-reset for graph replay determinism.
// ---------------------------------------------------------------------------
__global__ void __launch_bounds__(SPB) rank_kernel(float* __restrict__ out)
{
    __shared__ unsigned wlo[8], whi[8];
    __shared__ int offE[E], totE[E], baseE[E];

    const int b    = blockIdx.x;
    const int tid  = threadIdx.x;
    const int wid  = tid >> 5;
    const int lane = tid & 31;
    const int slot = b * SPB + tid;

    // ---- phase 1: local stable rank + per-block histogram ----
    const int e = g_exp[slot];
    unsigned lo = 0, hi = 0;
    packAdd(e, lo, hi);
    const unsigned mlo = lo, mhi = hi;

#pragma unroll
    for (int off = 1; off < 32; off <<= 1) {
        unsigned vlo = __shfl_up_sync(0xffffffffu, lo, off);
        unsigned vhi = __shfl_up_sync(0xffffffffu, hi, off);
        if (lane >= off) { lo += vlo; hi += vhi; }
    }
    if (lane == 31) { wlo[wid] = lo; whi[wid] = hi; }
    __syncthreads();

    unsigned plo = 0, phi = 0;
#pragma unroll
    for (int w2 = 0; w2 < 8; w2++)
        if (w2 < wid) { plo += wlo[w2]; phi += whi[w2]; }

    const int lrank = fieldOf(plo + lo - mlo, phi + hi - mhi, e);

    if (tid < E) {
        unsigned tlo = 0, thi = 0;
#pragma unroll
        for (int w2 = 0; w2 < 8; w2++) { tlo += wlo[w2]; thi += whi[w2]; }
        g_bhist[b * E + tid] = fieldOf(tlo, thi, tid);
    }

    // ---- global barrier across the 64 blocks ----
    __threadfence();
    __syncthreads();
    if (tid == 0) atomicAdd((int*)&g_sync, 1);
    if (tid == 0) while (g_sync < NHB) { }
    __syncthreads();
    __threadfence();

    // ---- phase 2: finalize ----
    if (tid < E) {
        int off = 0, tot = 0;
#pragma unroll
        for (int bb = 0; bb < NHB; bb++) {
            int h = g_bhist[bb * E + tid];
            if (bb < b) off += h;
            tot += h;
        }
        offE[tid] = off; totE[tid] = tot;
    }
    __syncthreads();
    if (tid == 0) {
        int s = 0;
#pragma unroll
        for (int ee = 0; ee < E; ee++) { baseE[ee] = s; s += totE[ee]; }
    }
    __syncthreads();

    const int pos = baseE[e] + offE[e] + lrank;
    g_pos[slot] = pos;
    out[OFF_IDX + pos] = (float)(slot >> 1);   // scatter_indices
    out[OFF_SC  + pos] = g_prob[slot];         // scores_sorted

    if (b == 0 && tid < E) out[OFF_CNT + tid] = (float)totE[tid];

    // ---- self-reset for next graph replay ----
    __syncthreads();
    if (tid == 0) {
        int d = atomicAdd(&g_done, 1);
        if (d == NHB - 1) { g_sync = 0; g_done = 0; }
    }
}

// ---------------------------------------------------------------------------
// Kernel C: scatter copy — read each token row once, write 2 destination rows.
// ---------------------------------------------------------------------------
__global__ void __launch_bounds__(256) scatter_kernel(
    const float* __restrict__ x, float* __restrict__ out)
{
    const int t = blockIdx.x;
    const int p0 = g_pos[2 * t];
    const int p1 = g_pos[2 * t + 1];
    const float4* __restrict__ src = (const float4*)x + (size_t)t * 1024;
    float4* __restrict__ d0 = (float4*)(out + OFF_XG) + (size_t)p0 * 1024;
    float4* __restrict__ d1 = (float4*)(out + OFF_XG) + (size_t)p1 * 1024;

    const int i = threadIdx.x;
    float4 v0 = src[i];
    float4 v1 = src[i + 256];
    float4 v2 = src[i + 512];
    float4 v3 = src[i + 768];
    __stcs(d0 + i,       v0);
    __stcs(d0 + i + 256, v1);
    __stcs(d0 + i + 512, v2);
    __stcs(d0 + i + 768, v3);
    __stcs(d1 + i,       v0);
    __stcs(d1 + i + 256, v1);
    __stcs(d1 + i + 512, v2);
    __stcs(d1 + i + 768, v3);
}

extern "C" void kernel_launch(void* const* d_in, const int* in_sizes, int n_in,
                              void* d_out, int out_size)
{
    const float* x = (const float*)d_in[0];
    const float* W = (const float*)d_in[1];
    if (n_in >= 2 && in_sizes[0] == E * D && in_sizes[1] == (int)((size_t)T * D)) {
        const float* tmp = x; x = W; W = tmp;
    }
    float* out = (float*)d_out;

    static int smem_set = 0;
    if (!smem_set) {
        cudaFuncSetAttribute(router_scores_kernel,
                             cudaFuncAttributeMaxDynamicSharedMemorySize,
                             E * D * (int)sizeof(float));
        smem_set = 1;
    }

    router_scores_kernel<<<SGRID, 512, E * D * sizeof(float)>>>(x, W);
    rank_kernel<<<NHB, SPB>>>(out);
    scatter_kernel<<<T, 256>>>(x, out);
}